// round 2
// baseline (speedup 1.0000x reference)
#include <cuda_runtime.h>
#include <math.h>

static inline int cdiv(int a, int b){ return (a + b - 1) / b; }

constexpr int kB = 64, kT = 256, kC = 53, kH = 64, kA = 128;
constexpr int kC2 = kC * kC;        // 2809
constexpr int kN1 = kC2 / 2;        // 1404
constexpr int kN2 = kC2 / 4;        // 702
constexpr int kM  = kB * kT;        // 16384

// ---------------- device scratch (static: no allocations allowed) ----------------
__device__ float g_u[192], g_v[192];
__device__ float g_whht[64 * 192];                 // w_hh transposed: [k][j]
__device__ float g_qw0t[64 * 128], g_qw1t[128 * 128], g_qw2t[128 * 128];
__device__ float g_kw0t[64 * 128], g_kw1t[128 * 128], g_kw2t[128 * 128];
__device__ float g_w0t[(size_t)kC2 * kN1];         // clf_w0^T : 2809 x 1404
__device__ float g_w1t[(size_t)kN1 * kN2];         // clf_w1^T : 1404 x 702
__device__ float g_z1[(size_t)kM * kN1];           // 16384 x 1404
__device__ float g_z2[(size_t)kM * kN2];           // 16384 x 702
__device__ float g_zbar[kB * kN2];

__device__ __forceinline__ float sigmoidf_(float x){ return 1.f / (1.f + __expf(-x)); }

// ---------------- prep: u,v and small weight transposes ----------------
__global__ void prep_small(const float* __restrict__ w_ih, const float* __restrict__ w_emb,
                           const float* __restrict__ b_emb, const float* __restrict__ b_ih,
                           const float* __restrict__ w_hh,
                           const float* __restrict__ qw0, const float* __restrict__ qw1, const float* __restrict__ qw2,
                           const float* __restrict__ kw0, const float* __restrict__ kw1, const float* __restrict__ kw2)
{
    int gt = blockIdx.x * blockDim.x + threadIdx.x;
    int gs = gridDim.x * blockDim.x;
    for (int j = gt; j < 192; j += gs){
        float su = 0.f, sv = 0.f;
        for (int e = 0; e < 64; e++){
            su += w_ih[j * 64 + e] * w_emb[e];
            sv += w_ih[j * 64 + e] * b_emb[e];
        }
        g_u[j] = su; g_v[j] = sv + b_ih[j];
    }
    for (int idx = gt; idx < 64 * 192; idx += gs){
        int k = idx / 192, j = idx - k * 192;
        g_whht[idx] = w_hh[j * 64 + k];
    }
    for (int idx = gt; idx < 64 * 128; idx += gs){
        int k = idx / 128, j = idx - k * 128;
        g_qw0t[idx] = qw0[j * 64 + k];
        g_kw0t[idx] = kw0[j * 64 + k];
    }
    for (int idx = gt; idx < 128 * 128; idx += gs){
        int k = idx / 128, j = idx - k * 128;
        g_qw1t[idx] = qw1[j * 128 + k];
        g_qw2t[idx] = qw2[j * 128 + k];
        g_kw1t[idx] = kw1[j * 128 + k];
        g_kw2t[idx] = kw2[j * 128 + k];
    }
}

__global__ void transpose_big(const float* __restrict__ clf_w0, const float* __restrict__ clf_w1)
{
    int gt = blockIdx.x * blockDim.x + threadIdx.x;
    int gs = gridDim.x * blockDim.x;
    for (size_t idx = gt; idx < (size_t)kC2 * kN1; idx += gs){
        int k = (int)(idx / kN1), j = (int)(idx - (size_t)k * kN1);
        g_w0t[idx] = clf_w0[(size_t)j * kC2 + k];
    }
    for (size_t idx = gt; idx < (size_t)kN1 * kN2; idx += gs){
        int k = (int)(idx / kN2), j = (int)(idx - (size_t)k * kN2);
        g_w1t[idx] = clf_w1[(size_t)j * kN1 + k];
    }
}

// ---------------- recurrent kernel: one CTA per batch ----------------
constexpr int S_H    = 0;                       // 53*64
constexpr int S_HGRU = S_H + kC * kH;           // 53*64
constexpr int S_B1   = S_HGRU + kC * kH;        // 53*128
constexpr int S_B2   = S_B1 + kC * kA;          // 53*128
constexpr int S_Q    = S_B2 + kC * kA;          // 53*128
constexpr int S_KK   = S_Q + kC * kA;           // 53*128
constexpr int S_TR   = S_KK + kC * kA;          // 53*56 (padded)
constexpr int S_FNC  = S_TR + kC * 56;          // 2809
constexpr int S_WHH  = S_FNC + kC2;             // 64*192
constexpr int S_GB   = S_WHH + 64 * 192;        // 2809
constexpr int S_UV   = S_GB + kC2;              // 384
constexpr int S_BHH  = S_UV + 384;              // 192
constexpr int S_PW   = S_BHH + 192;             // 64
constexpr int S_X    = S_PW + 64;               // 56
constexpr int S_RED  = S_X + 56;                // 40
constexpr int SM_FLOATS = S_RED + 40;
constexpr int SM_BYTES  = SM_FLOATS * 4;

template<int K, bool RELU>
__device__ __forceinline__ void mlp_gemm(float* __restrict__ outp, const float* __restrict__ inp,
                                         const float* __restrict__ Wt, const float* __restrict__ bias,
                                         int jj, int rg)
{
    const int c0 = rg * 27;
    const int nr = rg ? 26 : 27;
    float acc[27];
#pragma unroll
    for (int i = 0; i < 27; i++) acc[i] = 0.f;
    float w0 = Wt[0 * 128 + jj], w1 = Wt[1 * 128 + jj], w2 = Wt[2 * 128 + jj], w3 = Wt[3 * 128 + jj];
#pragma unroll 1
    for (int k = 0; k < K; k += 4){
        float n0, n1, n2, n3;
        if (k + 4 < K){
            n0 = Wt[(k + 4) * 128 + jj]; n1 = Wt[(k + 5) * 128 + jj];
            n2 = Wt[(k + 6) * 128 + jj]; n3 = Wt[(k + 7) * 128 + jj];
        } else { n0 = n1 = n2 = n3 = 0.f; }
#pragma unroll
        for (int ci = 0; ci < 27; ci++){
            if (ci < nr){
                const float4 a = *(const float4*)&inp[(c0 + ci) * K + k];
                acc[ci] = fmaf(a.x, w0, fmaf(a.y, w1, fmaf(a.z, w2, fmaf(a.w, w3, acc[ci]))));
            }
        }
        w0 = n0; w1 = n1; w2 = n2; w3 = n3;
    }
    const float bv = bias[jj];
#pragma unroll
    for (int ci = 0; ci < 27; ci++){
        if (ci < nr){
            float v = acc[ci] + bv;
            if (RELU) v = fmaxf(v, 0.f);
            outp[(c0 + ci) * 128 + jj] = v;
        }
    }
}

__global__ void recurrent_kernel(const float* __restrict__ x,
                                 const float* __restrict__ b_hh,
                                 const float* __restrict__ qb0, const float* __restrict__ qb1, const float* __restrict__ qb2,
                                 const float* __restrict__ kb0, const float* __restrict__ kb1, const float* __restrict__ kb2,
                                 const float* __restrict__ gate_bias,
                                 const float* __restrict__ pred_w, const float* __restrict__ pred_b,
                                 float* __restrict__ out_mix, float* __restrict__ out_fnc, float* __restrict__ out_pred)
{
    extern __shared__ float sm[];
    const int tid = threadIdx.x;
    const int b = blockIdx.x;

    for (int i = tid; i < kC * kH; i += 256) sm[S_H + i] = 0.f;
    for (int i = tid; i < kC2; i += 256){ sm[S_FNC + i] = 0.f; sm[S_GB + i] = gate_bias[i]; }
    for (int i = tid; i < 64 * 192; i += 256) sm[S_WHH + i] = g_whht[i];
    if (tid < 192){ sm[S_UV + tid] = g_u[tid]; sm[S_UV + 192 + tid] = g_v[tid]; sm[S_BHH + tid] = b_hh[tid]; }
    if (tid < 64) sm[S_PW + tid] = pred_w[tid];
    const float predb = pred_b[0];
    __syncthreads();

    const int hh = tid & 63, cg = tid >> 6;
    const int jj = tid & 127, rg = tid >> 7;

    for (int t = 0; t < kT; t++){
        if (tid < kC) sm[S_X + tid] = x[((size_t)b * kT + t) * kC + tid];
        __syncthreads();

        // ---- Stage A: gh = h @ w_hh^T + GRU fuse -> hgru ----
        {
            float aR[14], aZ[14], aN[14];
#pragma unroll
            for (int i = 0; i < 14; i++){ aR[i] = 0.f; aZ[i] = 0.f; aN[i] = 0.f; }
#pragma unroll 1
            for (int k = 0; k < 64; k += 4){
                float wr0 = sm[S_WHH + (k + 0) * 192 + hh];
                float wr1 = sm[S_WHH + (k + 1) * 192 + hh];
                float wr2 = sm[S_WHH + (k + 2) * 192 + hh];
                float wr3 = sm[S_WHH + (k + 3) * 192 + hh];
                float wz0 = sm[S_WHH + (k + 0) * 192 + 64 + hh];
                float wz1 = sm[S_WHH + (k + 1) * 192 + 64 + hh];
                float wz2 = sm[S_WHH + (k + 2) * 192 + 64 + hh];
                float wz3 = sm[S_WHH + (k + 3) * 192 + 64 + hh];
                float wn0 = sm[S_WHH + (k + 0) * 192 + 128 + hh];
                float wn1 = sm[S_WHH + (k + 1) * 192 + 128 + hh];
                float wn2 = sm[S_WHH + (k + 2) * 192 + 128 + hh];
                float wn3 = sm[S_WHH + (k + 3) * 192 + 128 + hh];
#pragma unroll
                for (int ci = 0; ci < 14; ci++){
                    int c = cg + 4 * ci;
                    if (c < kC){
                        const float4 hv = *(const float4*)&sm[S_H + c * 64 + k];
                        aR[ci] += hv.x * wr0 + hv.y * wr1 + hv.z * wr2 + hv.w * wr3;
                        aZ[ci] += hv.x * wz0 + hv.y * wz1 + hv.z * wz2 + hv.w * wz3;
                        aN[ci] += hv.x * wn0 + hv.y * wn1 + hv.z * wn2 + hv.w * wn3;
                    }
                }
            }
#pragma unroll
            for (int ci = 0; ci < 14; ci++){
                int c = cg + 4 * ci;
                if (c < kC){
                    float xi = sm[S_X + c];
                    float r = sigmoidf_(fmaf(xi, sm[S_UV + hh],       sm[S_UV + 192 + hh])       + aR[ci] + sm[S_BHH + hh]);
                    float z = sigmoidf_(fmaf(xi, sm[S_UV + 64 + hh],  sm[S_UV + 256 + hh])       + aZ[ci] + sm[S_BHH + 64 + hh]);
                    float n = tanhf(    fmaf(xi, sm[S_UV + 128 + hh], sm[S_UV + 320 + hh])       + r * (aN[ci] + sm[S_BHH + 128 + hh]));
                    sm[S_HGRU + c * 64 + hh] = (1.f - z) * n + z * sm[S_H + c * 64 + hh];
                }
            }
        }
        __syncthreads();

        // ---- Stage B: q and k MLPs ----
        mlp_gemm<64,  true >(sm + S_B1, sm + S_HGRU, g_qw0t, qb0, jj, rg); __syncthreads();
        mlp_gemm<128, true >(sm + S_B2, sm + S_B1,   g_qw1t, qb1, jj, rg); __syncthreads();
        mlp_gemm<128, false>(sm + S_Q,  sm + S_B2,   g_qw2t, qb2, jj, rg); __syncthreads();
        mlp_gemm<64,  true >(sm + S_B1, sm + S_HGRU, g_kw0t, kb0, jj, rg); __syncthreads();
        mlp_gemm<128, true >(sm + S_B2, sm + S_B1,   g_kw1t, kb1, jj, rg); __syncthreads();
        mlp_gemm<128, false>(sm + S_KK, sm + S_B2,   g_kw2t, kb2, jj, rg); __syncthreads();

        // ---- Stage C: transfer = q @ k^T ----
        {
            const int j = hh;
            if (j < kC){
                float acc[14];
#pragma unroll
                for (int i = 0; i < 14; i++) acc[i] = 0.f;
#pragma unroll 1
                for (int k = 0; k < 128; k += 4){
                    const float4 kv = *(const float4*)&sm[S_KK + j * 128 + k];
#pragma unroll
                    for (int ci = 0; ci < 14; ci++){
                        int c = cg + 4 * ci;
                        if (c < kC){
                            const float4 qv = *(const float4*)&sm[S_Q + c * 128 + k];
                            acc[ci] += qv.x * kv.x + qv.y * kv.y + qv.z * kv.z + qv.w * kv.w;
                        }
                    }
                }
#pragma unroll
                for (int ci = 0; ci < 14; ci++){
                    int c = cg + 4 * ci;
                    if (c < kC) sm[S_TR + c * 56 + j] = acc[ci];
                }
            }
        }
        __syncthreads();

        // ---- norm ----
        {
            float p = 0.f;
            for (int idx = tid; idx < kC2; idx += 256){
                int cc = idx / 53, dd = idx - cc * 53;
                float v = sm[S_TR + cc * 56 + dd];
                p = fmaf(v, v, p);
            }
#pragma unroll
            for (int o = 16; o; o >>= 1) p += __shfl_xor_sync(0xffffffffu, p, o);
            if ((tid & 31) == 0) sm[S_RED + (tid >> 5)] = p;
        }
        __syncthreads();
        if (tid == 0){
            float s = 0.f;
            for (int i = 0; i < 8; i++) s += sm[S_RED + i];
            sm[S_RED + 8] = 1.f / sqrtf(s);
        }
        __syncthreads();

        // ---- normalize + gate + emit mix + accumulate fnc ----
        {
            const float inv = sm[S_RED + 8];
            float* mix_bt = out_mix + ((size_t)b * kT + t) * kC2;
            for (int idx = tid; idx < kC2; idx += 256){
                int cc = idx / 53, dd = idx - cc * 53;
                float v = sm[S_TR + cc * 56 + dd] * inv;
                float gate = sigmoidf_(fabsf(v) + sm[S_GB + idx]);
                float val = v * gate;
                sm[S_TR + cc * 56 + dd] = val;
                mix_bt[idx] = val;
                sm[S_FNC + idx] += val;
            }
        }
        __syncthreads();

        // ---- Stage D: h_new = transfer @ hgru -> s_h ----
        {
            float acc[14];
#pragma unroll
            for (int i = 0; i < 14; i++) acc[i] = 0.f;
#pragma unroll 1
            for (int d = 0; d < 52; d += 4){
                float g0 = sm[S_HGRU + (d + 0) * 64 + hh];
                float g1 = sm[S_HGRU + (d + 1) * 64 + hh];
                float g2 = sm[S_HGRU + (d + 2) * 64 + hh];
                float g3 = sm[S_HGRU + (d + 3) * 64 + hh];
#pragma unroll
                for (int ci = 0; ci < 14; ci++){
                    int c = cg + 4 * ci;
                    if (c < kC){
                        const float4 tv = *(const float4*)&sm[S_TR + c * 56 + d];
                        acc[ci] += tv.x * g0 + tv.y * g1 + tv.z * g2 + tv.w * g3;
                    }
                }
            }
            {
                float g = sm[S_HGRU + 52 * 64 + hh];
#pragma unroll
                for (int ci = 0; ci < 14; ci++){
                    int c = cg + 4 * ci;
                    if (c < kC) acc[ci] += sm[S_TR + c * 56 + 52] * g;
                }
            }
#pragma unroll
            for (int ci = 0; ci < 14; ci++){
                int c = cg + 4 * ci;
                if (c < kC) sm[S_H + c * 64 + hh] = acc[ci];
            }
        }
        __syncthreads();

        // ---- predicted (uses h_new, only t < T-1) ----
        if (t < kT - 1 && tid < kC){
            float s2 = 0.f;
#pragma unroll
            for (int k = 0; k < 64; k += 4){
                const float4 hv = *(const float4*)&sm[S_H + tid * 64 + k];
                s2 += hv.x * sm[S_PW + k] + hv.y * sm[S_PW + k + 1] + hv.z * sm[S_PW + k + 2] + hv.w * sm[S_PW + k + 3];
            }
            out_pred[((size_t)b * (kT - 1) + t) * kC + tid] = s2 + predb;
        }
        __syncthreads();
    }

    for (int idx = tid; idx < kC2; idx += 256)
        out_fnc[(size_t)b * kC2 + idx] = sm[S_FNC + idx] * (1.f / 256.f);
}

// ---------------- big fp32 GEMM: C = relu?(A @ Bt + bias) ----------------
// A: M x K row-major, Bt: K x N row-major (pre-transposed weight), M % 128 == 0
template<bool RELU>
__global__ __launch_bounds__(256, 2) void sgemm_kernel(const float* __restrict__ Ag, const float* __restrict__ Bt,
                                                       const float* __restrict__ bias, float* __restrict__ Cg,
                                                       int M, int N, int K)
{
    __shared__ float As[16 * 136];
    __shared__ float Bs[16 * 128];
    const int tid = threadIdx.x;
    const int bn = blockIdx.x, bm = blockIdx.y;
    const int tx = tid & 15, ty = tid >> 4;

    float acc[8][8];
#pragma unroll
    for (int i = 0; i < 8; i++)
#pragma unroll
        for (int j = 0; j < 8; j++) acc[i][j] = 0.f;

    const int a_k = tid & 15;
    const int a_m = tid >> 4;
    const int b_n = tid & 127;
    const int b_k0 = tid >> 7;
    const float* Arow = Ag + (size_t)(bm * 128) * K;

    for (int k0 = 0; k0 < K; k0 += 16){
#pragma unroll
        for (int mi = 0; mi < 8; mi++){
            int m = a_m + 16 * mi;
            float v = (k0 + a_k < K) ? Arow[(size_t)m * K + k0 + a_k] : 0.f;
            As[a_k * 136 + m] = v;
        }
#pragma unroll
        for (int ki = 0; ki < 8; ki++){
            int kk = b_k0 + 2 * ki;
            int n = bn * 128 + b_n;
            float v = (k0 + kk < K && n < N) ? Bt[(size_t)(k0 + kk) * N + n] : 0.f;
            Bs[kk * 128 + b_n] = v;
        }
        __syncthreads();
#pragma unroll
        for (int kk = 0; kk < 16; kk++){
            float ra[8], rb[8];
            *(float4*)&ra[0] = *(const float4*)&As[kk * 136 + ty * 8];
            *(float4*)&ra[4] = *(const float4*)&As[kk * 136 + ty * 8 + 4];
            *(float4*)&rb[0] = *(const float4*)&Bs[kk * 128 + tx * 8];
            *(float4*)&rb[4] = *(const float4*)&Bs[kk * 128 + tx * 8 + 4];
#pragma unroll
            for (int i = 0; i < 8; i++)
#pragma unroll
                for (int j = 0; j < 8; j++)
                    acc[i][j] = fmaf(ra[i], rb[j], acc[i][j]);
        }
        __syncthreads();
    }
#pragma unroll
    for (int i = 0; i < 8; i++){
        int m = bm * 128 + ty * 8 + i;
#pragma unroll
        for (int j = 0; j < 8; j++){
            int n = bn * 128 + tx * 8 + j;
            if (n < N){
                float v = acc[i][j] + bias[n];
                if (RELU) v = fmaxf(v, 0.f);
                Cg[(size_t)m * N + n] = v;
            }
        }
    }
}

// ---------------- z2 mean over T, logits, x copy ----------------
__global__ void zbar_kernel()
{
    const int b = blockIdx.x;
    for (int j = threadIdx.x; j < kN2; j += blockDim.x){
        float s = 0.f;
        for (int t = 0; t < kT; t++) s += g_z2[((size_t)b * kT + t) * kN2 + j];
        g_zbar[b * kN2 + j] = s * (1.f / (float)kT);
    }
}

__global__ void logits_kernel(const float* __restrict__ w2, const float* __restrict__ b2, float* __restrict__ out)
{
    const int i = threadIdx.x;
    if (i < 2 * kB){
        int b = i >> 1, o = i & 1;
        float s = 0.f;
        for (int j = 0; j < kN2; j++) s += g_zbar[b * kN2 + j] * w2[o * kN2 + j];
        out[i] = s + b2[o];
    }
}

__global__ void xcopy_kernel(const float* __restrict__ x, float* __restrict__ outx)
{
    const int n = kB * (kT - 1) * kC;
    for (int idx = blockIdx.x * blockDim.x + threadIdx.x; idx < n; idx += gridDim.x * blockDim.x){
        int b = idx / ((kT - 1) * kC);
        int r = idx - b * (kT - 1) * kC;
        outx[idx] = x[(size_t)b * kT * kC + kC + r];
    }
}

// ---------------- launch ----------------
extern "C" void kernel_launch(void* const* d_in, const int* in_sizes, int n_in,
                              void* d_out, int out_size)
{
    const float* x        = (const float*)d_in[0];
    const float* w_emb    = (const float*)d_in[1];
    const float* b_emb    = (const float*)d_in[2];
    const float* w_ih     = (const float*)d_in[3];
    const float* w_hh     = (const float*)d_in[4];
    const float* b_ih     = (const float*)d_in[5];
    const float* b_hh     = (const float*)d_in[6];
    const float* q_w0     = (const float*)d_in[7];
    const float* q_b0     = (const float*)d_in[8];
    const float* q_w1     = (const float*)d_in[9];
    const float* q_b1     = (const float*)d_in[10];
    const float* q_w2     = (const float*)d_in[11];
    const float* q_b2     = (const float*)d_in[12];
    const float* k_w0     = (const float*)d_in[13];
    const float* k_b0     = (const float*)d_in[14];
    const float* k_w1     = (const float*)d_in[15];
    const float* k_b1     = (const float*)d_in[16];
    const float* k_w2     = (const float*)d_in[17];
    const float* k_b2     = (const float*)d_in[18];
    const float* gate_bias= (const float*)d_in[19];
    const float* pred_w   = (const float*)d_in[20];
    const float* pred_b   = (const float*)d_in[21];
    const float* clf_w0   = (const float*)d_in[22];
    const float* clf_b0   = (const float*)d_in[23];
    const float* clf_w1   = (const float*)d_in[24];
    const float* clf_b1   = (const float*)d_in[25];
    const float* clf_w2   = (const float*)d_in[26];
    const float* clf_b2   = (const float*)d_in[27];

    float* out      = (float*)d_out;
    float* out_log  = out;                                        // 128
    float* out_fnc  = out + 2 * kB;                               // 64*2809
    float* out_mix  = out_fnc + (size_t)kB * kC2;                 // 64*256*2809
    float* out_pred = out_mix + (size_t)kB * kT * kC2;            // 64*255*53
    float* out_x    = out_pred + (size_t)kB * (kT - 1) * kC;      // 64*255*53

    cudaFuncSetAttribute(recurrent_kernel, cudaFuncAttributeMaxDynamicSharedMemorySize, SM_BYTES);

    prep_small<<<48, 256>>>(w_ih, w_emb, b_emb, b_ih, w_hh, q_w0, q_w1, q_w2, k_w0, k_w1, k_w2);
    transpose_big<<<2048, 256>>>(clf_w0, clf_w1);

    recurrent_kernel<<<kB, 256, SM_BYTES>>>(x, b_hh, q_b0, q_b1, q_b2, k_b0, k_b1, k_b2,
                                            gate_bias, pred_w, pred_b,
                                            out_mix, out_fnc, out_pred);

    float *pz1, *pz2, *pw0t, *pw1t;
    cudaGetSymbolAddress((void**)&pz1,  g_z1);
    cudaGetSymbolAddress((void**)&pz2,  g_z2);
    cudaGetSymbolAddress((void**)&pw0t, g_w0t);
    cudaGetSymbolAddress((void**)&pw1t, g_w1t);

    sgemm_kernel<true><<<dim3(cdiv(kN1, 128), kM / 128), 256>>>(out_mix, pw0t, clf_b0, pz1, kM, kN1, kC2);
    sgemm_kernel<true><<<dim3(cdiv(kN2, 128), kM / 128), 256>>>(pz1,     pw1t, clf_b1, pz2, kM, kN2, kN1);

    zbar_kernel<<<kB, 256>>>();
    logits_kernel<<<1, 128>>>(clf_w2, clf_b2, out_log);
    xcopy_kernel<<<512, 256>>>(x, out_x);
}

// round 3
// speedup vs baseline: 1.4695x; 1.4695x over previous
#include <cuda_runtime.h>
#include <math.h>
#include <stdint.h>

static inline int cdiv(int a, int b){ return (a + b - 1) / b; }

constexpr int kB = 64, kT = 256, kC = 53, kH = 64, kA = 128;
constexpr int kC2 = kC * kC;        // 2809
constexpr int kN1 = kC2 / 2;        // 1404
constexpr int kN2 = kC2 / 4;        // 702
constexpr int kM  = kB * kT;        // 16384

// padded dims for tensor-core GEMMs
constexpr int kKP0 = 2816;          // K pad of 2809 (88*32)
constexpr int kNP1 = 1408;          // N pad of 1404 (11*128), also K of gemm2 (44*32)
constexpr int kNP2 = 768;           // N pad of 702 (6*128)

// ---------------- device scratch (static: no allocations allowed) ----------------
__device__ float g_u[192], g_v[192];
__device__ float g_whht[64 * 192];
__device__ float g_qw0t[64 * 128], g_qw1t[128 * 128], g_qw2t[128 * 128];
__device__ float g_kw0t[64 * 128], g_kw1t[128 * 128], g_kw2t[128 * 128];
__device__ float g_mixp[(size_t)kM * kKP0];        // tf32-cvt'd padded mix (A of gemm1)
__device__ float g_w0p[(size_t)kNP1 * kKP0];       // tf32 padded clf_w0 (N,K)
__device__ float g_w1p[(size_t)kNP2 * kNP1];       // tf32 padded clf_w1 (N,K)
__device__ float g_z1[(size_t)kM * kNP1];
__device__ float g_z2[(size_t)kM * kNP2];
__device__ float g_zbar[kB * kN2];

__device__ __forceinline__ float sigmoidf_(float x){ return 1.f / (1.f + __expf(-x)); }

__device__ __forceinline__ uint32_t cvt_tf32(float x){
    uint32_t y; asm("cvt.rna.tf32.f32 %0, %1;" : "=r"(y) : "f"(x)); return y;
}
__device__ __forceinline__ void st_peer(float* p, float v, uint32_t peer){
    uint32_t l = (uint32_t)__cvta_generic_to_shared(p);
    uint32_t r; asm("mapa.shared::cluster.u32 %0, %1, %2;" : "=r"(r) : "r"(l), "r"(peer));
    asm volatile("st.shared::cluster.f32 [%0], %1;" :: "r"(r), "f"(v) : "memory");
}
__device__ __forceinline__ void cluster_sync_(){
    asm volatile("barrier.cluster.arrive.aligned;" ::: "memory");
    asm volatile("barrier.cluster.wait.aligned;" ::: "memory");
}
__device__ __forceinline__ void cp_async16(void* smem, const void* gmem){
    uint32_t s = (uint32_t)__cvta_generic_to_shared(smem);
    asm volatile("cp.async.cg.shared.global [%0], [%1], 16;" :: "r"(s), "l"(gmem) : "memory");
}
__device__ __forceinline__ void mma_tf32(float* c, const uint32_t* a, const uint32_t* b){
    asm volatile("mma.sync.aligned.m16n8k8.row.col.f32.tf32.tf32.f32 "
        "{%0,%1,%2,%3}, {%4,%5,%6,%7}, {%8,%9}, {%0,%1,%2,%3};"
        : "+f"(c[0]), "+f"(c[1]), "+f"(c[2]), "+f"(c[3])
        : "r"(a[0]), "r"(a[1]), "r"(a[2]), "r"(a[3]), "r"(b[0]), "r"(b[1]));
}

// ---------------- prep: u,v and small weight transposes ----------------
__global__ void prep_small(const float* __restrict__ w_ih, const float* __restrict__ w_emb,
                           const float* __restrict__ b_emb, const float* __restrict__ b_ih,
                           const float* __restrict__ w_hh,
                           const float* __restrict__ qw0, const float* __restrict__ qw1, const float* __restrict__ qw2,
                           const float* __restrict__ kw0, const float* __restrict__ kw1, const float* __restrict__ kw2)
{
    int gt = blockIdx.x * blockDim.x + threadIdx.x;
    int gs = gridDim.x * blockDim.x;
    for (int j = gt; j < 192; j += gs){
        float su = 0.f, sv = 0.f;
        for (int e = 0; e < 64; e++){
            su += w_ih[j * 64 + e] * w_emb[e];
            sv += w_ih[j * 64 + e] * b_emb[e];
        }
        g_u[j] = su; g_v[j] = sv + b_ih[j];
    }
    for (int idx = gt; idx < 64 * 192; idx += gs){
        int k = idx / 192, j = idx - k * 192;
        g_whht[idx] = w_hh[j * 64 + k];
    }
    for (int idx = gt; idx < 64 * 128; idx += gs){
        int k = idx / 128, j = idx - k * 128;
        g_qw0t[idx] = qw0[j * 64 + k];
        g_kw0t[idx] = kw0[j * 64 + k];
    }
    for (int idx = gt; idx < 128 * 128; idx += gs){
        int k = idx / 128, j = idx - k * 128;
        g_qw1t[idx] = qw1[j * 128 + k];
        g_qw2t[idx] = qw2[j * 128 + k];
        g_kw1t[idx] = kw1[j * 128 + k];
        g_kw2t[idx] = kw2[j * 128 + k];
    }
}

// pack classifier weights: zero-padded, tf32-converted, (N,K) row-major
__global__ void pack_clf(const float* __restrict__ clf_w0, const float* __restrict__ clf_w1)
{
    size_t gt = (size_t)blockIdx.x * blockDim.x + threadIdx.x;
    size_t gs = (size_t)gridDim.x * blockDim.x;
    for (size_t idx = gt; idx < (size_t)kNP1 * kKP0; idx += gs){
        int j = (int)(idx / kKP0), k = (int)(idx - (size_t)j * kKP0);
        float v = (j < kN1 && k < kC2) ? clf_w0[(size_t)j * kC2 + k] : 0.f;
        g_w0p[idx] = __uint_as_float(cvt_tf32(v));
    }
    for (size_t idx = gt; idx < (size_t)kNP2 * kNP1; idx += gs){
        int j = (int)(idx / kNP1), k = (int)(idx - (size_t)j * kNP1);
        float v = (j < kN2 && k < kN1) ? clf_w1[(size_t)j * kN1 + k] : 0.f;
        g_w1p[idx] = __uint_as_float(cvt_tf32(v));
    }
}

// ---------------- recurrent kernel: 2-CTA cluster per batch ----------------
constexpr int S_H    = 0;                       // 53*64
constexpr int S_HGRU = S_H + kC * kH;           // 53*64 (full: peer half pushed)
constexpr int S_B1   = S_HGRU + kC * kH;        // 53*128 (own rows)
constexpr int S_B2   = S_B1 + kC * kA;
constexpr int S_Q    = S_B2 + kC * kA;
constexpr int S_KK   = S_Q + kC * kA;           // full: peer half pushed
constexpr int S_TR   = S_KK + kC * kA;          // 53*56 own rows
constexpr int S_FNC  = S_TR + kC * 56;          // 2809 (own region used)
constexpr int S_WHH  = S_FNC + kC2;             // 64*192
constexpr int S_GB   = S_WHH + 64 * 192;        // 2809
constexpr int S_UV   = S_GB + kC2;              // 384
constexpr int S_BHH  = S_UV + 384;              // 192
constexpr int S_PW   = S_BHH + 192;             // 64
constexpr int S_X    = S_PW + 64;               // 56
constexpr int S_RED  = S_X + 56;                // 16
constexpr int SM_FLOATS = S_RED + 16;
constexpr int SM_BYTES  = SM_FLOATS * 4;

template<int K, bool RELU, bool MIRROR>
__device__ __forceinline__ void mlp_gemm(float* __restrict__ outp, const float* __restrict__ inp,
                                         const float* __restrict__ Wt, const float* __restrict__ bias,
                                         int jj, int rg, int c_lo, int c_n, uint32_t peer)
{
    const int base = rg * 14;
    int nr = c_n - base; if (nr > 14) nr = 14; if (nr < 0) nr = 0;
    float acc[14];
#pragma unroll
    for (int i = 0; i < 14; i++) acc[i] = 0.f;
    float w0 = Wt[0 * 128 + jj], w1 = Wt[1 * 128 + jj], w2 = Wt[2 * 128 + jj], w3 = Wt[3 * 128 + jj];
#pragma unroll 1
    for (int k = 0; k < K; k += 4){
        float n0, n1, n2, n3;
        if (k + 4 < K){
            n0 = Wt[(k + 4) * 128 + jj]; n1 = Wt[(k + 5) * 128 + jj];
            n2 = Wt[(k + 6) * 128 + jj]; n3 = Wt[(k + 7) * 128 + jj];
        } else { n0 = n1 = n2 = n3 = 0.f; }
#pragma unroll
        for (int ci = 0; ci < 14; ci++){
            if (ci < nr){
                const float4 a = *(const float4*)&inp[(c_lo + base + ci) * K + k];
                acc[ci] = fmaf(a.x, w0, fmaf(a.y, w1, fmaf(a.z, w2, fmaf(a.w, w3, acc[ci]))));
            }
        }
        w0 = n0; w1 = n1; w2 = n2; w3 = n3;
    }
    const float bv = bias[jj];
#pragma unroll
    for (int ci = 0; ci < 14; ci++){
        if (ci < nr){
            float v = acc[ci] + bv;
            if (RELU) v = fmaxf(v, 0.f);
            const int c = c_lo + base + ci;
            outp[c * 128 + jj] = v;
            if (MIRROR) st_peer(&outp[c * 128 + jj], v, peer);
        }
    }
}

__global__ void __cluster_dims__(2, 1, 1)
recurrent_kernel(const float* __restrict__ x,
                 const float* __restrict__ b_hh,
                 const float* __restrict__ qb0, const float* __restrict__ qb1, const float* __restrict__ qb2,
                 const float* __restrict__ kb0, const float* __restrict__ kb1, const float* __restrict__ kb2,
                 const float* __restrict__ gate_bias,
                 const float* __restrict__ pred_w, const float* __restrict__ pred_b,
                 float* __restrict__ out_mix, float* __restrict__ out_fnc, float* __restrict__ out_pred)
{
    extern __shared__ float sm[];
    const int tid = threadIdx.x;
    const int b = blockIdx.x >> 1;
    const uint32_t rank = blockIdx.x & 1;
    const uint32_t peer = rank ^ 1;
    const int c_lo = rank ? 27 : 0;
    const int c_n  = rank ? 26 : 27;

    for (int i = tid; i < kC * kH; i += 256) sm[S_H + i] = 0.f;
    for (int i = tid; i < kC2; i += 256){ sm[S_FNC + i] = 0.f; sm[S_GB + i] = gate_bias[i]; }
    for (int i = tid; i < 64 * 192; i += 256) sm[S_WHH + i] = g_whht[i];
    if (tid < 192){ sm[S_UV + tid] = g_u[tid]; sm[S_UV + 192 + tid] = g_v[tid]; sm[S_BHH + tid] = b_hh[tid]; }
    if (tid < 64) sm[S_PW + tid] = pred_w[tid];
    const float predb = pred_b[0];
    __syncthreads();

    const int hh = tid & 63, cg = tid >> 6;
    const int jj = tid & 127, rg = tid >> 7;
    const int nloc = c_n * 53;

    cluster_sync_();   // everyone initialized before any remote traffic

    for (int t = 0; t < kT; t++){
        if (tid < kC) sm[S_X + tid] = x[((size_t)b * kT + t) * kC + tid];
        __syncthreads();

        // ---- Stage A: GRU rows (own half); push hgru half to peer ----
        {
            float aR[7], aZ[7], aN[7];
#pragma unroll
            for (int i = 0; i < 7; i++){ aR[i] = 0.f; aZ[i] = 0.f; aN[i] = 0.f; }
#pragma unroll 1
            for (int k = 0; k < 64; k += 4){
                float wr0 = sm[S_WHH + (k + 0) * 192 + hh];
                float wr1 = sm[S_WHH + (k + 1) * 192 + hh];
                float wr2 = sm[S_WHH + (k + 2) * 192 + hh];
                float wr3 = sm[S_WHH + (k + 3) * 192 + hh];
                float wz0 = sm[S_WHH + (k + 0) * 192 + 64 + hh];
                float wz1 = sm[S_WHH + (k + 1) * 192 + 64 + hh];
                float wz2 = sm[S_WHH + (k + 2) * 192 + 64 + hh];
                float wz3 = sm[S_WHH + (k + 3) * 192 + 64 + hh];
                float wn0 = sm[S_WHH + (k + 0) * 192 + 128 + hh];
                float wn1 = sm[S_WHH + (k + 1) * 192 + 128 + hh];
                float wn2 = sm[S_WHH + (k + 2) * 192 + 128 + hh];
                float wn3 = sm[S_WHH + (k + 3) * 192 + 128 + hh];
#pragma unroll
                for (int ci = 0; ci < 7; ci++){
                    int cl = cg + 4 * ci;
                    if (cl < c_n){
                        const float4 hv = *(const float4*)&sm[S_H + (c_lo + cl) * 64 + k];
                        aR[ci] += hv.x * wr0 + hv.y * wr1 + hv.z * wr2 + hv.w * wr3;
                        aZ[ci] += hv.x * wz0 + hv.y * wz1 + hv.z * wz2 + hv.w * wz3;
                        aN[ci] += hv.x * wn0 + hv.y * wn1 + hv.z * wn2 + hv.w * wn3;
                    }
                }
            }
#pragma unroll
            for (int ci = 0; ci < 7; ci++){
                int cl = cg + 4 * ci;
                if (cl < c_n){
                    int c = c_lo + cl;
                    float xi = sm[S_X + c];
                    float r = sigmoidf_(fmaf(xi, sm[S_UV + hh],       sm[S_UV + 192 + hh]) + aR[ci] + sm[S_BHH + hh]);
                    float z = sigmoidf_(fmaf(xi, sm[S_UV + 64 + hh],  sm[S_UV + 256 + hh]) + aZ[ci] + sm[S_BHH + 64 + hh]);
                    float n = tanhf(    fmaf(xi, sm[S_UV + 128 + hh], sm[S_UV + 320 + hh]) + r * (aN[ci] + sm[S_BHH + 128 + hh]));
                    float hg = (1.f - z) * n + z * sm[S_H + c * 64 + hh];
                    sm[S_HGRU + c * 64 + hh] = hg;
                    st_peer(&sm[S_HGRU + c * 64 + hh], hg, peer);
                }
            }
        }
        __syncthreads();

        // ---- Stage B: q and k MLPs on own rows; push final k to peer ----
        mlp_gemm<64,  true , false>(sm + S_B1, sm + S_HGRU, g_qw0t, qb0, jj, rg, c_lo, c_n, peer); __syncthreads();
        mlp_gemm<128, true , false>(sm + S_B2, sm + S_B1,   g_qw1t, qb1, jj, rg, c_lo, c_n, peer); __syncthreads();
        mlp_gemm<128, false, false>(sm + S_Q,  sm + S_B2,   g_qw2t, qb2, jj, rg, c_lo, c_n, peer); __syncthreads();
        mlp_gemm<64,  true , false>(sm + S_B1, sm + S_HGRU, g_kw0t, kb0, jj, rg, c_lo, c_n, peer); __syncthreads();
        mlp_gemm<128, true , false>(sm + S_B2, sm + S_B1,   g_kw1t, kb1, jj, rg, c_lo, c_n, peer); __syncthreads();
        mlp_gemm<128, false, true >(sm + S_KK, sm + S_B2,   g_kw2t, kb2, jj, rg, c_lo, c_n, peer);

        cluster_sync_();   // full k + full hgru now visible everywhere

        // ---- Stage C: transfer own rows x all 53 cols ----
        {
            const int j = hh;
            if (j < kC){
                float acc[7];
#pragma unroll
                for (int i = 0; i < 7; i++) acc[i] = 0.f;
#pragma unroll 1
                for (int k = 0; k < 128; k += 4){
                    const float4 kv = *(const float4*)&sm[S_KK + j * 128 + k];
#pragma unroll
                    for (int ci = 0; ci < 7; ci++){
                        int cl = cg + 4 * ci;
                        if (cl < c_n){
                            const float4 qv = *(const float4*)&sm[S_Q + (c_lo + cl) * 128 + k];
                            acc[ci] += qv.x * kv.x + qv.y * kv.y + qv.z * kv.z + qv.w * kv.w;
                        }
                    }
                }
#pragma unroll
                for (int ci = 0; ci < 7; ci++){
                    int cl = cg + 4 * ci;
                    if (cl < c_n) sm[S_TR + (c_lo + cl) * 56 + j] = acc[ci];
                }
            }
        }
        __syncthreads();

        // ---- norm: partial over own rows, exchange with peer ----
        {
            float p = 0.f;
            for (int idx = tid; idx < nloc; idx += 256){
                int cc = c_lo + idx / 53, dd = idx % 53;
                float v = sm[S_TR + cc * 56 + dd];
                p = fmaf(v, v, p);
            }
#pragma unroll
            for (int o = 16; o; o >>= 1) p += __shfl_xor_sync(0xffffffffu, p, o);
            if ((tid & 31) == 0) sm[S_RED + (tid >> 5)] = p;
        }
        __syncthreads();
        if (tid == 0){
            float s = 0.f;
            for (int i = 0; i < 8; i++) s += sm[S_RED + i];
            sm[S_RED + 10] = s;
            st_peer(&sm[S_RED + 11], s, peer);
        }
        cluster_sync_();
        const float inv = rsqrtf(sm[S_RED + 10] + sm[S_RED + 11]);

        // ---- normalize + gate + emit mix (+tf32 copy) + fnc ----
        {
            float* mix_bt = out_mix + ((size_t)b * kT + t) * kC2;
            float* mixp_bt = g_mixp + ((size_t)b * kT + t) * kKP0;
            for (int idx = tid; idx < nloc; idx += 256){
                int glob = c_lo * 53 + idx;
                int cc = c_lo + idx / 53, dd = idx % 53;
                float v = sm[S_TR + cc * 56 + dd] * inv;
                float gate = sigmoidf_(fabsf(v) + sm[S_GB + glob]);
                float val = v * gate;
                sm[S_TR + cc * 56 + dd] = val;
                mix_bt[glob] = val;
                mixp_bt[glob] = __uint_as_float(cvt_tf32(val));
                sm[S_FNC + glob] += val;
            }
        }
        __syncthreads();

        // ---- Stage D: h_new own rows = transfer(own) @ hgru(full) ----
        {
            float acc[7];
#pragma unroll
            for (int i = 0; i < 7; i++) acc[i] = 0.f;
#pragma unroll 1
            for (int d = 0; d < 52; d += 4){
                float g0 = sm[S_HGRU + (d + 0) * 64 + hh];
                float g1 = sm[S_HGRU + (d + 1) * 64 + hh];
                float g2 = sm[S_HGRU + (d + 2) * 64 + hh];
                float g3 = sm[S_HGRU + (d + 3) * 64 + hh];
#pragma unroll
                for (int ci = 0; ci < 7; ci++){
                    int cl = cg + 4 * ci;
                    if (cl < c_n){
                        const float4 tv = *(const float4*)&sm[S_TR + (c_lo + cl) * 56 + d];
                        acc[ci] += tv.x * g0 + tv.y * g1 + tv.z * g2 + tv.w * g3;
                    }
                }
            }
            {
                float g = sm[S_HGRU + 52 * 64 + hh];
#pragma unroll
                for (int ci = 0; ci < 7; ci++){
                    int cl = cg + 4 * ci;
                    if (cl < c_n) acc[ci] += sm[S_TR + (c_lo + cl) * 56 + 52] * g;
                }
            }
#pragma unroll
            for (int ci = 0; ci < 7; ci++){
                int cl = cg + 4 * ci;
                if (cl < c_n) sm[S_H + (c_lo + cl) * 64 + hh] = acc[ci];
            }
        }
        __syncthreads();

        // ---- predicted (h_new, t < T-1), own rows ----
        if (t < kT - 1 && tid < c_n){
            int c = c_lo + tid;
            float s2 = 0.f;
#pragma unroll
            for (int k = 0; k < 64; k += 4){
                const float4 hv = *(const float4*)&sm[S_H + c * 64 + k];
                s2 += hv.x * sm[S_PW + k] + hv.y * sm[S_PW + k + 1] + hv.z * sm[S_PW + k + 2] + hv.w * sm[S_PW + k + 3];
            }
            out_pred[((size_t)b * (kT - 1) + t) * kC + c] = s2 + predb;
        }

        cluster_sync_();   // end of step: peer done reading our pushes
    }

    for (int idx = tid; idx < nloc; idx += 256){
        int glob = c_lo * 53 + idx;
        out_fnc[(size_t)b * kC2 + glob] = sm[S_FNC + glob] * (1.f / 256.f);
    }
}

// ---------------- tf32 tensor-core GEMM: C = relu(A @ B^T + bias) ----------------
// A: M x K row-major (tf32 bits), B: Npad x K row-major (tf32 bits, zero-padded rows)
// C: M x Nstore. Nstore = gridDim.x*128 exactly. K % 32 == 0, M % 128 == 0.
template<bool RELU, bool CVT>
__global__ __launch_bounds__(256, 2) void mma_gemm(const float* __restrict__ A, const float* __restrict__ B,
                                                   const float* __restrict__ bias, float* __restrict__ C,
                                                   int M, int Nstore, int Nreal, int K)
{
    extern __shared__ float smg[];
    float* As = smg;            // 2 x 128 x 36
    float* Bs = smg + 2 * 4608;

    const int tid = threadIdx.x;
    const int wid = tid >> 5, lane = tid & 31;
    const int warp_m = wid & 3, warp_n = wid >> 2;
    const int g = lane >> 2, l4 = lane & 3;
    const int bm = blockIdx.y * 128, bn = blockIdx.x * 128;

    const float* Ab = A + (size_t)bm * K;
    const float* Bb = B + (size_t)bn * K;

    float acc[2][8][4];
#pragma unroll
    for (int i = 0; i < 2; i++)
#pragma unroll
        for (int j = 0; j < 8; j++)
#pragma unroll
            for (int q = 0; q < 4; q++) acc[i][j][q] = 0.f;

    const int nk = K >> 5;

    auto load_tile = [&](int kt, int buf){
        const int k0 = kt * 32;
        float* as = As + buf * 4608;
        float* bs = Bs + buf * 4608;
#pragma unroll
        for (int i = 0; i < 4; i++){
            int ch = tid + i * 256;
            int row = ch >> 3;
            int ko = (ch & 7) * 4;
            cp_async16(&as[row * 36 + ko], Ab + (size_t)row * K + k0 + ko);
            cp_async16(&bs[row * 36 + ko], Bb + (size_t)row * K + k0 + ko);
        }
        asm volatile("cp.async.commit_group;" ::: "memory");
    };

    load_tile(0, 0);

    for (int kt = 0; kt < nk; kt++){
        const int buf = kt & 1;
        if (kt + 1 < nk){
            load_tile(kt + 1, buf ^ 1);
            asm volatile("cp.async.wait_group 1;" ::: "memory");
        } else {
            asm volatile("cp.async.wait_group 0;" ::: "memory");
        }
        __syncthreads();

        const float* as = As + buf * 4608;
        const float* bs = Bs + buf * 4608;
#pragma unroll
        for (int s = 0; s < 4; s++){
            const int kk = s * 8 + l4;
            uint32_t a[2][4], bf[8][2];
            const int r0 = warp_m * 32 + g;
            a[0][0] = __float_as_uint(as[(r0     ) * 36 + kk]);
            a[0][1] = __float_as_uint(as[(r0 +  8) * 36 + kk]);
            a[0][2] = __float_as_uint(as[(r0     ) * 36 + kk + 4]);
            a[0][3] = __float_as_uint(as[(r0 +  8) * 36 + kk + 4]);
            a[1][0] = __float_as_uint(as[(r0 + 16) * 36 + kk]);
            a[1][1] = __float_as_uint(as[(r0 + 24) * 36 + kk]);
            a[1][2] = __float_as_uint(as[(r0 + 16) * 36 + kk + 4]);
            a[1][3] = __float_as_uint(as[(r0 + 24) * 36 + kk + 4]);
#pragma unroll
            for (int nt = 0; nt < 8; nt++){
                const int nb = warp_n * 64 + nt * 8 + g;
                bf[nt][0] = __float_as_uint(bs[nb * 36 + kk]);
                bf[nt][1] = __float_as_uint(bs[nb * 36 + kk + 4]);
            }
#pragma unroll
            for (int mt = 0; mt < 2; mt++)
#pragma unroll
                for (int nt = 0; nt < 8; nt++)
                    mma_tf32(acc[mt][nt], a[mt], bf[nt]);
        }
        __syncthreads();
    }

#pragma unroll
    for (int mt = 0; mt < 2; mt++){
#pragma unroll
        for (int nt = 0; nt < 8; nt++){
            const int row = bm + warp_m * 32 + mt * 16 + g;
            const int col = bn + warp_n * 64 + nt * 8 + 2 * l4;
            const float b0v = (col < Nreal) ? bias[col] : 0.f;
            const float b1v = (col + 1 < Nreal) ? bias[col + 1] : 0.f;
            float v00 = acc[mt][nt][0] + b0v;
            float v01 = acc[mt][nt][1] + b1v;
            float v10 = acc[mt][nt][2] + b0v;
            float v11 = acc[mt][nt][3] + b1v;
            if (RELU){
                v00 = fmaxf(v00, 0.f); v01 = fmaxf(v01, 0.f);
                v10 = fmaxf(v10, 0.f); v11 = fmaxf(v11, 0.f);
            }
            if (CVT){
                v00 = __uint_as_float(cvt_tf32(v00)); v01 = __uint_as_float(cvt_tf32(v01));
                v10 = __uint_as_float(cvt_tf32(v10)); v11 = __uint_as_float(cvt_tf32(v11));
            }
            C[(size_t)row * Nstore + col]           = v00;
            C[(size_t)row * Nstore + col + 1]       = v01;
            C[(size_t)(row + 8) * Nstore + col]     = v10;
            C[(size_t)(row + 8) * Nstore + col + 1] = v11;
        }
    }
}

// ---------------- z2 mean over T, logits, x copy ----------------
__global__ void zbar_kernel()
{
    const int b = blockIdx.x;
    for (int j = threadIdx.x; j < kN2; j += blockDim.x){
        float s = 0.f;
        for (int t = 0; t < kT; t++) s += g_z2[((size_t)b * kT + t) * kNP2 + j];
        g_zbar[b * kN2 + j] = s * (1.f / (float)kT);
    }
}

__global__ void logits_kernel(const float* __restrict__ w2, const float* __restrict__ b2, float* __restrict__ out)
{
    __shared__ float red[8];
    const int b = blockIdx.x >> 1, o = blockIdx.x & 1;
    float s = 0.f;
    for (int j = threadIdx.x; j < kN2; j += 256)
        s += g_zbar[b * kN2 + j] * w2[o * kN2 + j];
#pragma unroll
    for (int off = 16; off; off >>= 1) s += __shfl_xor_sync(0xffffffffu, s, off);
    if ((threadIdx.x & 31) == 0) red[threadIdx.x >> 5] = s;
    __syncthreads();
    if (threadIdx.x == 0){
        float t = 0.f;
        for (int i = 0; i < 8; i++) t += red[i];
        out[b * 2 + o] = t + b2[o];
    }
}

__global__ void xcopy_kernel(const float* __restrict__ x, float* __restrict__ outx)
{
    const int n = kB * (kT - 1) * kC;
    for (int idx = blockIdx.x * blockDim.x + threadIdx.x; idx < n; idx += gridDim.x * blockDim.x){
        int b = idx / ((kT - 1) * kC);
        int r = idx - b * (kT - 1) * kC;
        outx[idx] = x[(size_t)b * kT * kC + kC + r];
    }
}

// ---------------- launch ----------------
extern "C" void kernel_launch(void* const* d_in, const int* in_sizes, int n_in,
                              void* d_out, int out_size)
{
    const float* x        = (const float*)d_in[0];
    const float* w_emb    = (const float*)d_in[1];
    const float* b_emb    = (const float*)d_in[2];
    const float* w_ih     = (const float*)d_in[3];
    const float* w_hh     = (const float*)d_in[4];
    const float* b_ih     = (const float*)d_in[5];
    const float* b_hh     = (const float*)d_in[6];
    const float* q_w0     = (const float*)d_in[7];
    const float* q_b0     = (const float*)d_in[8];
    const float* q_w1     = (const float*)d_in[9];
    const float* q_b1     = (const float*)d_in[10];
    const float* q_w2     = (const float*)d_in[11];
    const float* q_b2     = (const float*)d_in[12];
    const float* k_w0     = (const float*)d_in[13];
    const float* k_b0     = (const float*)d_in[14];
    const float* k_w1     = (const float*)d_in[15];
    const float* k_b1     = (const float*)d_in[16];
    const float* k_w2     = (const float*)d_in[17];
    const float* k_b2     = (const float*)d_in[18];
    const float* gate_bias= (const float*)d_in[19];
    const float* pred_w   = (const float*)d_in[20];
    const float* pred_b   = (const float*)d_in[21];
    const float* clf_w0   = (const float*)d_in[22];
    const float* clf_b0   = (const float*)d_in[23];
    const float* clf_w1   = (const float*)d_in[24];
    const float* clf_b1   = (const float*)d_in[25];
    const float* clf_w2   = (const float*)d_in[26];
    const float* clf_b2   = (const float*)d_in[27];

    float* out      = (float*)d_out;
    float* out_log  = out;                                        // 128
    float* out_fnc  = out + 2 * kB;                               // 64*2809
    float* out_mix  = out_fnc + (size_t)kB * kC2;                 // 64*256*2809
    float* out_pred = out_mix + (size_t)kB * kT * kC2;            // 64*255*53
    float* out_x    = out_pred + (size_t)kB * (kT - 1) * kC;      // 64*255*53

    cudaFuncSetAttribute(recurrent_kernel, cudaFuncAttributeMaxDynamicSharedMemorySize, SM_BYTES);
    cudaFuncSetAttribute(mma_gemm<true, true>,  cudaFuncAttributeMaxDynamicSharedMemorySize, 2 * 2 * 4608 * 4);
    cudaFuncSetAttribute(mma_gemm<true, false>, cudaFuncAttributeMaxDynamicSharedMemorySize, 2 * 2 * 4608 * 4);

    prep_small<<<48, 256>>>(w_ih, w_emb, b_emb, b_ih, w_hh, q_w0, q_w1, q_w2, k_w0, k_w1, k_w2);
    pack_clf<<<2048, 256>>>(clf_w0, clf_w1);

    recurrent_kernel<<<2 * kB, 256, SM_BYTES>>>(x, b_hh, q_b0, q_b1, q_b2, k_b0, k_b1, k_b2,
                                                gate_bias, pred_w, pred_b,
                                                out_mix, out_fnc, out_pred);

    float *pz1, *pz2, *pw0p, *pw1p, *pmixp;
    cudaGetSymbolAddress((void**)&pz1,   g_z1);
    cudaGetSymbolAddress((void**)&pz2,   g_z2);
    cudaGetSymbolAddress((void**)&pw0p,  g_w0p);
    cudaGetSymbolAddress((void**)&pw1p,  g_w1p);
    cudaGetSymbolAddress((void**)&pmixp, g_mixp);

    const int smem_gemm = 2 * 2 * 4608 * 4;
    mma_gemm<true, true ><<<dim3(kNP1 / 128, kM / 128), 256, smem_gemm>>>(pmixp, pw0p, clf_b0, pz1, kM, kNP1, kN1, kKP0);
    mma_gemm<true, false><<<dim3(kNP2 / 128, kM / 128), 256, smem_gemm>>>(pz1,   pw1p, clf_b1, pz2, kM, kNP2, kN2, kNP1);

    zbar_kernel<<<kB, 256>>>();
    logits_kernel<<<2 * kB, 256>>>(clf_w2, clf_b2, out_log);
    xcopy_kernel<<<512, 256>>>(x, out_x);
}